// round 3
// baseline (speedup 1.0000x reference)
#include <cuda_runtime.h>
#include <cuda_bf16.h>
#include <math.h>
#include <stdint.h>

// ---------------- problem constants ----------------
#define N_ATOMS 50000
#define N_EDGES 800000
#define NB 128
#define NG 32
#define NPER 5000
#define TBL 8192                 // table entries per conv
#define DMAX 6.5f

typedef unsigned long long ull;

// ---------------- device scratch (static, no runtime alloc) ----------------
__device__ float d_h  [(size_t)N_ATOMS * NB];
__device__ float d_hf [(size_t)N_ATOMS * NB];
__device__ float d_agg[(size_t)N_ATOMS * NB];
__device__ float d_u  [(size_t)N_ATOMS * NB];
__device__ float d_z  [(size_t)N_ATOMS * 64];
__device__ float d_y  [N_ATOMS];
__device__ float d_dist[N_EDGES];
__device__ float d_table[(size_t)3 * TBL * NB];   // 12.6 MB
__device__ int   d_deg[N_ATOMS];
__device__ int   d_cur[N_ATOMS];
__device__ int   d_off[N_ATOMS + 1];
__device__ int   d_eidx[N_EDGES];
__device__ int   d_srcs[N_EDGES];    // src per CSR slot
__device__ float d_tf  [N_EDGES];    // table coord per CSR slot

// ---------------- helpers ----------------
__device__ __forceinline__ ull ffma2(ull a, ull b, ull c) {
    ull d;
    asm("fma.rn.f32x2 %0, %1, %2, %3;" : "=l"(d) : "l"(a), "l"(b), "l"(c));
    return d;
}
__device__ __forceinline__ ull dup2(float x) {
    ull d; asm("mov.b64 %0, {%1, %1};" : "=l"(d) : "f"(x)); return d;
}
__device__ __forceinline__ float2 unpack2(ull v) {
    float2 r; asm("mov.b64 {%0, %1}, %2;" : "=f"(r.x), "=f"(r.y) : "l"(v)); return r;
}
__device__ __forceinline__ float sspf(float x) {
    // softplus(x) - log(2), numerically stable
    float ax = fabsf(x);
    return fmaxf(x, 0.0f) + log1pf(__expf(-ax)) - 0.69314718055994531f;
}

// ---------------- init h = embed[r] ----------------
__global__ void init_h_kernel(const int* __restrict__ r, const float* __restrict__ embed,
                              float* __restrict__ h) {
    int idx = blockIdx.x * blockDim.x + threadIdx.x;   // over float4 elements
    if (idx < N_ATOMS * (NB / 4)) {
        int row = idx >> 5;
        int c4  = idx & 31;
        int t = r[row];
        ((float4*)h)[idx] = ((const float4*)embed)[(size_t)t * 32 + c4];
    }
}

// ---------------- per-edge distance ----------------
__global__ void compute_d_kernel(const float* __restrict__ xyz, const int* __restrict__ a,
                                 float* __restrict__ dist) {
    int e = blockIdx.x * 256 + threadIdx.x;
    if (e < N_EDGES) {
        int i = a[2 * e], j = a[2 * e + 1];
        float dx = xyz[3 * i + 0] - xyz[3 * j + 0];
        float dy = xyz[3 * i + 1] - xyz[3 * j + 1];
        float dz = xyz[3 * i + 2] - xyz[3 * j + 2];
        dist[e] = sqrtf(dx * dx + dy * dy + dz * dz + 1e-12f);
    }
}

// ---------------- CSR build ----------------
__global__ void count_kernel(const int* __restrict__ a, int* __restrict__ deg) {
    int e = blockIdx.x * 256 + threadIdx.x;
    if (e < N_EDGES) atomicAdd(&deg[a[2 * e]], 1);
}

__global__ void scan_kernel(const int* __restrict__ deg, int* __restrict__ off) {
    __shared__ int part[1024];
    const int CH = 49;   // ceil(50000/1024)
    int t = threadIdx.x;
    int start = t * CH;
    int end = min(start + CH, N_ATOMS);
    int s = 0;
    for (int i = start; i < end; i++) s += deg[i];
    part[t] = s;
    __syncthreads();
    for (int o = 1; o < 1024; o <<= 1) {
        int v = (t >= o) ? part[t - o] : 0;
        __syncthreads();
        part[t] += v;
        __syncthreads();
    }
    int run = (t > 0) ? part[t - 1] : 0;
    for (int i = start; i < end; i++) { off[i] = run; run += deg[i]; }
    if (t == 1023) off[N_ATOMS] = run;
}

__global__ void fill_kernel(const int* __restrict__ a, const int* __restrict__ off,
                            int* __restrict__ cur, int* __restrict__ eidx) {
    int e = blockIdx.x * 256 + threadIdx.x;
    if (e < N_EDGES) {
        int dst = a[2 * e];
        int p = off[dst] + atomicAdd(&cur[dst], 1);
        eidx[p] = e;
    }
}

// per-dst insertion sort of edge ids -> deterministic accumulation order
__global__ void sort_kernel(const int* __restrict__ off, int* __restrict__ eidx) {
    int v = blockIdx.x * 256 + threadIdx.x;
    if (v < N_ATOMS) {
        int s = off[v], t = off[v + 1];
        for (int i = s + 1; i < t; i++) {
            int key = eidx[i];
            int j = i - 1;
            while (j >= s && eidx[j] > key) { eidx[j + 1] = eidx[j]; j--; }
            eidx[j + 1] = key;
        }
    }
}

// materialize per-slot src + table coord (conv-invariant)
__global__ void csr_finalize_kernel(const int* __restrict__ eidx, const int* __restrict__ a,
                                    const float* __restrict__ dist,
                                    int* __restrict__ srcs, float* __restrict__ tf) {
    int j = blockIdx.x * 256 + threadIdx.x;
    if (j < N_EDGES) {
        int e = eidx[j];
        srcs[j] = a[2 * e + 1];
        const float SCALE = (float)(TBL - 1) / DMAX;
        tf[j] = fminf(dist[e] * SCALE, (float)(TBL - 1) - 1e-3f);
    }
}

// ---------------- build W(d) tables: one block (128 thr) per (entry, conv) ----------------
__global__ void build_table_kernel(const float* __restrict__ fw1, const float* __restrict__ fb1,
                                   const float* __restrict__ fw2, const float* __restrict__ fb2,
                                   float* __restrict__ table) {
    __shared__ float sg[NG];
    __shared__ float st[NB];
    int entry = blockIdx.x;
    int conv  = blockIdx.y;
    int c = threadIdx.x;
    float dval = (float)entry * (DMAX / (float)(TBL - 1));
    const float step = 5.0f / 31.0f;
    const float coeff = -0.5f / (step * step);
    if (c < NG) {
        float dd = dval - step * (float)c;
        sg[c] = __expf(coeff * dd * dd);
    }
    __syncthreads();
    const float* w1 = fw1 + (size_t)conv * NG * NB;
    float acc = fb1[conv * NB + c];
#pragma unroll
    for (int k = 0; k < NG; k++) acc += sg[k] * w1[k * NB + c];
    st[c] = sspf(acc);
    __syncthreads();
    const float* w2 = fw2 + (size_t)conv * NB * NB;
    float acc2 = fb2[conv * NB + c];
#pragma unroll 8
    for (int m = 0; m < NB; m++) acc2 += st[m] * w2[m * NB + c];
    table[((size_t)conv * TBL + entry) * NB + c] = acc2;
}

// ---------------- edge gather: agg[dst] = sum_e hf[src_e] * W(d_e) ----------------
// one warp per dst atom, no atomics, deterministic order
__global__ void __launch_bounds__(256)
gather_kernel(const int* __restrict__ off, const int* __restrict__ srcs,
              const float* __restrict__ tf, const float* __restrict__ table,
              const float* __restrict__ hf, float* __restrict__ agg) {
    int w = (blockIdx.x * 256 + threadIdx.x) >> 5;
    int lane = threadIdx.x & 31;
    if (w >= N_ATOMS) return;
    int s = off[w], t = off[w + 1];
    float4 acc = make_float4(0.f, 0.f, 0.f, 0.f);
    for (int j = s; j < t; j++) {
        int src = __ldg(&srcs[j]);
        float tfv = __ldg(&tf[j]);
        int i0 = (int)tfv;
        float f = tfv - (float)i0;
        const float4* t0 = (const float4*)(table + (size_t)i0 * NB);
        float4 w0 = __ldg(&t0[lane]);
        float4 w1 = __ldg(&t0[lane + 32]);   // row i0+1 (contiguous)
        float4 hv = __ldg(&((const float4*)(hf + (size_t)src * NB))[lane]);
        float wx = w0.x + f * (w1.x - w0.x);
        float wy = w0.y + f * (w1.y - w0.y);
        float wz = w0.z + f * (w1.z - w0.z);
        float ww = w0.w + f * (w1.w - w0.w);
        acc.x += wx * hv.x;
        acc.y += wy * hv.y;
        acc.z += wz * hv.z;
        acc.w += ww * hv.w;
    }
    ((float4*)(agg + (size_t)w * NB))[lane] = acc;
}

// ---------------- generic fused GEMM: C = [ssp](A @ B + bias) [+= C] ----------------
template<int COLS>
struct GemmSmem {
    ull   sA2[128][64 + 2];       // dup-transposed A tile
    float sB[128][COLS];
    float sbias[COLS];
};

template<int COLS, bool ACT, bool RES>
__global__ void __launch_bounds__(256, 1)
gemm_kernel(const float* __restrict__ A, const float* __restrict__ B,
            const float* __restrict__ bias, float* __restrict__ C, int N) {
    extern __shared__ char smem_raw[];
    GemmSmem<COLS>& S = *reinterpret_cast<GemmSmem<COLS>*>(smem_raw);
    const int tid = threadIdx.x;
    const int row0 = blockIdx.x * 64;

    for (int idx = tid; idx < 128 * COLS / 4; idx += 256)
        ((float4*)S.sB)[idx] = ((const float4*)B)[idx];
    if (tid < COLS) S.sbias[tid] = bias[tid];

    for (int idx = tid; idx < 64 * 32; idx += 256) {
        int rr = idx >> 5;
        int k4 = idx & 31;
        float4 v = make_float4(0.f, 0.f, 0.f, 0.f);
        if (row0 + rr < N) v = ((const float4*)(A + (size_t)(row0 + rr) * 128))[k4];
        int k = k4 * 4;
        S.sA2[k + 0][rr] = dup2(v.x);
        S.sA2[k + 1][rr] = dup2(v.y);
        S.sA2[k + 2][rr] = dup2(v.z);
        S.sA2[k + 3][rr] = dup2(v.w);
    }
    __syncthreads();

    const int eg = tid >> 4;       // row group: 4 rows
    const int jg = tid & 15;       // col group: pairs at jg*2 + 32u
    const int r0 = eg * 4;
    constexpr int NU = COLS / 32;

    ull acc[4][NU];
#pragma unroll
    for (int u = 0; u < NU; u++) {
        ull b0 = *(const ull*)&S.sbias[jg * 2 + 32 * u];
#pragma unroll
        for (int r = 0; r < 4; r++) acc[r][u] = b0;
    }

#pragma unroll 4
    for (int k = 0; k < 128; k++) {
        ulonglong2 ta = *(const ulonglong2*)&S.sA2[k][r0];
        ulonglong2 tb = *(const ulonglong2*)&S.sA2[k][r0 + 2];
#pragma unroll
        for (int u = 0; u < NU; u++) {
            ull w = *(const ull*)&S.sB[k][jg * 2 + 32 * u];
            acc[0][u] = ffma2(ta.x, w, acc[0][u]);
            acc[1][u] = ffma2(ta.y, w, acc[1][u]);
            acc[2][u] = ffma2(tb.x, w, acc[2][u]);
            acc[3][u] = ffma2(tb.y, w, acc[3][u]);
        }
    }

#pragma unroll
    for (int r = 0; r < 4; r++) {
        int row = row0 + r0 + r;
        if (row >= N) continue;
#pragma unroll
        for (int u = 0; u < NU; u++) {
            int c = jg * 2 + 32 * u;
            float2 v = unpack2(acc[r][u]);
            if (ACT) { v.x = sspf(v.x); v.y = sspf(v.y); }
            float2* cp = (float2*)&C[(size_t)row * COLS + c];
            if (RES) { float2 o = *cp; v.x += o.x; v.y += o.y; }
            *cp = v;
        }
    }
}

// ---------------- readout: per-atom dot, then deterministic group sums ----------------
__global__ void final_dot_kernel(const float* __restrict__ z, const float* __restrict__ aw2,
                                 float* __restrict__ y) {
    int atom = (blockIdx.x * 256 + threadIdx.x) >> 5;
    int lane = threadIdx.x & 31;
    if (atom >= N_ATOMS) return;
    const float* zr = z + (size_t)atom * 64;
    float v = zr[lane] * aw2[lane] + zr[lane + 32] * aw2[lane + 32];
#pragma unroll
    for (int o = 16; o > 0; o >>= 1) v += __shfl_xor_sync(0xffffffffu, v, o);
    if (lane == 0) y[atom] = v;
}

__global__ void group_sum_kernel(const float* __restrict__ y, const float* __restrict__ ab2,
                                 float* __restrict__ out) {
    __shared__ float s[256];
    int g = blockIdx.x;
    int t = threadIdx.x;
    const float* yg = y + (size_t)g * NPER;
    float acc = 0.f;
    for (int i = t; i < NPER; i += 256) acc += yg[i];   // fixed order -> deterministic
    s[t] = acc;
    __syncthreads();
    for (int o = 128; o > 0; o >>= 1) {
        if (t < o) s[t] += s[t + o];
        __syncthreads();
    }
    if (t == 0) out[g] = s[0] + (float)NPER * ab2[0];
}

// ---------------- host launch ----------------
extern "C" void kernel_launch(void* const* d_in, const int* in_sizes, int n_in,
                              void* d_out, int out_size) {
    const int*   r    = (const int*)d_in[0];
    const float* xyz  = (const float*)d_in[1];
    const int*   a    = (const int*)d_in[2];
    int wi = (in_sizes[3] == 1) ? 4 : 3;   // skip n_per scalar if present
    const float* embed = (const float*)d_in[wi + 0];
    const float* fw1   = (const float*)d_in[wi + 1];
    const float* fb1   = (const float*)d_in[wi + 2];
    const float* fw2   = (const float*)d_in[wi + 3];
    const float* fb2   = (const float*)d_in[wi + 4];
    const float* afw   = (const float*)d_in[wi + 5];
    const float* afb   = (const float*)d_in[wi + 6];
    const float* ow1   = (const float*)d_in[wi + 7];
    const float* ob1   = (const float*)d_in[wi + 8];
    const float* ow2   = (const float*)d_in[wi + 9];
    const float* ob2   = (const float*)d_in[wi + 10];
    const float* aw1   = (const float*)d_in[wi + 11];
    const float* ab1   = (const float*)d_in[wi + 12];
    const float* aw2   = (const float*)d_in[wi + 13];
    const float* ab2   = (const float*)d_in[wi + 14];

    float *h_p, *hf_p, *agg_p, *u_p, *z_p, *y_p, *dist_p, *tab_p, *tf_p;
    int *deg_p, *cur_p, *off_p, *eidx_p, *srcs_p;
    cudaGetSymbolAddress((void**)&h_p,    d_h);
    cudaGetSymbolAddress((void**)&hf_p,   d_hf);
    cudaGetSymbolAddress((void**)&agg_p,  d_agg);
    cudaGetSymbolAddress((void**)&u_p,    d_u);
    cudaGetSymbolAddress((void**)&z_p,    d_z);
    cudaGetSymbolAddress((void**)&y_p,    d_y);
    cudaGetSymbolAddress((void**)&dist_p, d_dist);
    cudaGetSymbolAddress((void**)&tab_p,  d_table);
    cudaGetSymbolAddress((void**)&deg_p,  d_deg);
    cudaGetSymbolAddress((void**)&cur_p,  d_cur);
    cudaGetSymbolAddress((void**)&off_p,  d_off);
    cudaGetSymbolAddress((void**)&eidx_p, d_eidx);
    cudaGetSymbolAddress((void**)&srcs_p, d_srcs);
    cudaGetSymbolAddress((void**)&tf_p,   d_tf);

    cudaFuncSetAttribute(gemm_kernel<128, false, false>, cudaFuncAttributeMaxDynamicSharedMemorySize, (int)sizeof(GemmSmem<128>));
    cudaFuncSetAttribute(gemm_kernel<128, true,  false>, cudaFuncAttributeMaxDynamicSharedMemorySize, (int)sizeof(GemmSmem<128>));
    cudaFuncSetAttribute(gemm_kernel<128, false, true >, cudaFuncAttributeMaxDynamicSharedMemorySize, (int)sizeof(GemmSmem<128>));
    cudaFuncSetAttribute(gemm_kernel<64,  true,  false>, cudaFuncAttributeMaxDynamicSharedMemorySize, (int)sizeof(GemmSmem<64>));

    const int GEMM_GRID = (N_ATOMS + 63) / 64;
    const int EB = N_EDGES / 256;           // 3125
    const int AB = (N_ATOMS + 255) / 256;   // 196
    const int WARP_GRID = (N_ATOMS * 32 + 255) / 256;  // warp per atom

    cudaMemsetAsync(deg_p, 0, sizeof(int) * N_ATOMS, 0);
    cudaMemsetAsync(cur_p, 0, sizeof(int) * N_ATOMS, 0);

    init_h_kernel<<<(N_ATOMS * 32 + 255) / 256, 256>>>(r, embed, h_p);
    compute_d_kernel<<<EB, 256>>>(xyz, a, dist_p);

    // CSR build (int atomics only; per-dst sort => deterministic fp order)
    count_kernel<<<EB, 256>>>(a, deg_p);
    scan_kernel<<<1, 1024>>>(deg_p, off_p);
    fill_kernel<<<EB, 256>>>(a, off_p, cur_p, eidx_p);
    sort_kernel<<<AB, 256>>>(off_p, eidx_p);
    csr_finalize_kernel<<<EB, 256>>>(eidx_p, a, dist_p, srcs_p, tf_p);

    // W(d) lookup tables for all 3 convs
    {
        dim3 g(TBL, 3);
        build_table_kernel<<<g, 128>>>(fw1, fb1, fw2, fb2, tab_p);
    }

    for (int i = 0; i < 3; i++) {
        gemm_kernel<128, false, false><<<GEMM_GRID, 256, sizeof(GemmSmem<128>)>>>(
            h_p, afw + (size_t)i * 128 * 128, afb + (size_t)i * 128, hf_p, N_ATOMS);
        gather_kernel<<<WARP_GRID, 256>>>(off_p, srcs_p, tf_p,
                                          tab_p + (size_t)i * TBL * NB, hf_p, agg_p);
        gemm_kernel<128, true, false><<<GEMM_GRID, 256, sizeof(GemmSmem<128>)>>>(
            agg_p, ow1 + (size_t)i * 128 * 128, ob1 + (size_t)i * 128, u_p, N_ATOMS);
        gemm_kernel<128, false, true><<<GEMM_GRID, 256, sizeof(GemmSmem<128>)>>>(
            u_p, ow2 + (size_t)i * 128 * 128, ob2 + (size_t)i * 128, h_p, N_ATOMS);
    }

    gemm_kernel<64, true, false><<<GEMM_GRID, 256, sizeof(GemmSmem<64>)>>>(
        h_p, aw1, ab1, z_p, N_ATOMS);
    final_dot_kernel<<<WARP_GRID, 256>>>(z_p, aw2, y_p);
    group_sum_kernel<<<10, 256>>>(y_p, ab2, (float*)d_out);
}

// round 5
// speedup vs baseline: 1.0737x; 1.0737x over previous
#include <cuda_runtime.h>
#include <cuda_bf16.h>
#include <math.h>
#include <stdint.h>

// ---------------- problem constants ----------------
#define N_ATOMS 50000
#define N_EDGES 800000
#define NB 128
#define NG 32
#define NPER 5000
#define TBL 8192                 // table entries per conv
#define DMAX 6.5f
#define ENT 32                   // entries per table-build block

typedef unsigned long long ull;

// ---------------- device scratch (static, no runtime alloc) ----------------
__device__ float d_h  [(size_t)N_ATOMS * NB];
__device__ float d_hf [(size_t)N_ATOMS * NB];
__device__ float d_agg[(size_t)N_ATOMS * NB];
__device__ float d_u  [(size_t)N_ATOMS * NB];
__device__ float d_z  [(size_t)N_ATOMS * 64];
__device__ float d_y  [N_ATOMS];
__device__ float d_dist[N_EDGES];
__device__ float d_table[(size_t)3 * TBL * NB];   // 12.6 MB
__device__ int   d_deg[N_ATOMS];
__device__ int   d_cur[N_ATOMS];
__device__ int   d_off[N_ATOMS + 1];
__device__ int   d_eidx[N_EDGES];
__device__ int   d_srcs[N_EDGES];    // src per CSR slot
__device__ float d_tf  [N_EDGES];    // table coord per CSR slot
__device__ int   d_bsum[256];
__device__ int   d_boff[256];

// ---------------- helpers ----------------
__device__ __forceinline__ ull ffma2(ull a, ull b, ull c) {
    ull d;
    asm("fma.rn.f32x2 %0, %1, %2, %3;" : "=l"(d) : "l"(a), "l"(b), "l"(c));
    return d;
}
__device__ __forceinline__ ull dup2(float x) {
    ull d; asm("mov.b64 %0, {%1, %1};" : "=l"(d) : "f"(x)); return d;
}
__device__ __forceinline__ float2 unpack2(ull v) {
    float2 r; asm("mov.b64 {%0, %1}, %2;" : "=f"(r.x), "=f"(r.y) : "l"(v)); return r;
}
__device__ __forceinline__ float sspf(float x) {
    // softplus(x) - log(2), numerically stable
    float ax = fabsf(x);
    return fmaxf(x, 0.0f) + log1pf(__expf(-ax)) - 0.69314718055994531f;
}

// ---------------- init h = embed[r] ----------------
__global__ void init_h_kernel(const int* __restrict__ r, const float* __restrict__ embed,
                              float* __restrict__ h) {
    int idx = blockIdx.x * blockDim.x + threadIdx.x;   // over float4 elements
    if (idx < N_ATOMS * (NB / 4)) {
        int row = idx >> 5;
        int c4  = idx & 31;
        int t = r[row];
        ((float4*)h)[idx] = ((const float4*)embed)[(size_t)t * 32 + c4];
    }
}

// ---------------- fused: per-edge distance + degree count ----------------
__global__ void d_count_kernel(const float* __restrict__ xyz, const int* __restrict__ a,
                               float* __restrict__ dist, int* __restrict__ deg) {
    int e = blockIdx.x * 256 + threadIdx.x;
    if (e < N_EDGES) {
        int2 ij = ((const int2*)a)[e];
        float dx = xyz[3 * ij.x + 0] - xyz[3 * ij.y + 0];
        float dy = xyz[3 * ij.x + 1] - xyz[3 * ij.y + 1];
        float dz = xyz[3 * ij.x + 2] - xyz[3 * ij.y + 2];
        dist[e] = sqrtf(dx * dx + dy * dy + dz * dz + 1e-12f);
        atomicAdd(&deg[ij.x], 1);
    }
}

// ---------------- hierarchical scan ----------------
__global__ void scan_bsum_kernel(const int* __restrict__ deg, int* __restrict__ bsum) {
    __shared__ int s[256];
    int t = threadIdx.x;
    int i = blockIdx.x * 256 + t;
    s[t] = (i < N_ATOMS) ? deg[i] : 0;
    __syncthreads();
    for (int o = 128; o > 0; o >>= 1) {
        if (t < o) s[t] += s[t + o];
        __syncthreads();
    }
    if (t == 0) bsum[blockIdx.x] = s[0];
}

__global__ void scan_boff_kernel(const int* __restrict__ bsum, int* __restrict__ boff, int nb) {
    __shared__ int s[256];
    int t = threadIdx.x;
    int v = (t < nb) ? bsum[t] : 0;
    s[t] = v;
    __syncthreads();
    for (int o = 1; o < 256; o <<= 1) {
        int u = (t >= o) ? s[t - o] : 0;
        __syncthreads();
        s[t] += u;
        __syncthreads();
    }
    if (t < nb) boff[t] = s[t] - v;   // exclusive
}

__global__ void scan_off_kernel(const int* __restrict__ deg, const int* __restrict__ boff,
                                int* __restrict__ off) {
    __shared__ int s[256];
    int t = threadIdx.x;
    int i = blockIdx.x * 256 + t;
    int v = (i < N_ATOMS) ? deg[i] : 0;
    s[t] = v;
    __syncthreads();
    for (int o = 1; o < 256; o <<= 1) {
        int u = (t >= o) ? s[t - o] : 0;
        __syncthreads();
        s[t] += u;
        __syncthreads();
    }
    if (i < N_ATOMS) off[i] = boff[blockIdx.x] + s[t] - v;  // exclusive
    if (blockIdx.x == 0 && t == 0) off[N_ATOMS] = N_EDGES;
}

__global__ void fill_kernel(const int* __restrict__ a, const int* __restrict__ off,
                            int* __restrict__ cur, int* __restrict__ eidx) {
    int e = blockIdx.x * 256 + threadIdx.x;
    if (e < N_EDGES) {
        int dst = a[2 * e];
        int p = off[dst] + atomicAdd(&cur[dst], 1);
        eidx[p] = e;
    }
}

// per-dst insertion sort (deterministic order) + materialize srcs/tf
__global__ void sort_finalize_kernel(const int* __restrict__ off, int* __restrict__ eidx,
                                     const int* __restrict__ a, const float* __restrict__ dist,
                                     int* __restrict__ srcs, float* __restrict__ tf) {
    int v = blockIdx.x * 256 + threadIdx.x;
    if (v < N_ATOMS) {
        int s = off[v], t = off[v + 1];
        for (int i = s + 1; i < t; i++) {
            int key = eidx[i];
            int j = i - 1;
            while (j >= s && eidx[j] > key) { eidx[j + 1] = eidx[j]; j--; }
            eidx[j + 1] = key;
        }
        const float SCALE = (float)(TBL - 1) / DMAX;
        for (int j = s; j < t; j++) {
            int e = eidx[j];
            srcs[j] = a[2 * e + 1];
            tf[j] = fminf(dist[e] * SCALE, (float)(TBL - 1) - 1e-3f);
        }
    }
}

// ---------------- build W(d) tables: ENT entries per block, weights in smem ----------------
struct TblSmem {
    float sw1[NG][NB];       // 16 KB
    float sw2[NB][NB];       // 64 KB
    float sg[ENT][NG];       // 4 KB
    float st[ENT][NB];       // 16 KB
    float sb1[NB];
    float sb2[NB];
};

__global__ void __launch_bounds__(256, 1)
build_table_kernel(const float* __restrict__ fw1, const float* __restrict__ fb1,
                   const float* __restrict__ fw2, const float* __restrict__ fb2,
                   float* __restrict__ table) {
    extern __shared__ char smem_raw[];
    TblSmem& S = *reinterpret_cast<TblSmem*>(smem_raw);
    const int tid = threadIdx.x;
    const int conv = blockIdx.y;
    const int e_base = blockIdx.x * ENT;

    const float* w1 = fw1 + (size_t)conv * NG * NB;
    const float* w2 = fw2 + (size_t)conv * NB * NB;
    for (int idx = tid; idx < NG * NB / 4; idx += 256)
        ((float4*)S.sw1)[idx] = ((const float4*)w1)[idx];
    for (int idx = tid; idx < NB * NB / 4; idx += 256)
        ((float4*)S.sw2)[idx] = ((const float4*)w2)[idx];
    if (tid < NB) { S.sb1[tid] = fb1[conv * NB + tid]; S.sb2[tid] = fb2[conv * NB + tid]; }

    // gaussians for ENT entries
    const float step = 5.0f / 31.0f;
    const float coeff = -0.5f / (step * step);
    const float dstep = DMAX / (float)(TBL - 1);
    for (int idx = tid; idx < ENT * NG; idx += 256) {
        int e = idx >> 5, k = idx & 31;
        float dd = (float)(e_base + e) * dstep - step * (float)k;
        S.sg[e][k] = __expf(coeff * dd * dd);
    }
    __syncthreads();

    // phase 1: st[e][c] = ssp(g[e] @ w1 + b1)
    for (int idx = tid; idx < ENT * NB; idx += 256) {
        int e = idx >> 7, c = idx & 127;
        float acc = S.sb1[c];
#pragma unroll
        for (int k = 0; k < NG; k++) acc += S.sg[e][k] * S.sw1[k][c];
        S.st[e][c] = sspf(acc);
    }
    __syncthreads();

    // phase 2: W[e][c] = st[e] @ w2 + b2 ; thread: 2 entries x 4 col-pairs
    const int eg = tid >> 4;              // 0..15 -> entries eg, eg+16
    const int cg = tid & 15;              // col pairs cg+16u (u=0..3)
    ull acc[2][4];
#pragma unroll
    for (int u = 0; u < 4; u++) {
        ull b0 = *(const ull*)&S.sb2[(cg + 16 * u) * 2];
        acc[0][u] = b0; acc[1][u] = b0;
    }
#pragma unroll 4
    for (int m = 0; m < NB; m++) {
        ull t0 = dup2(S.st[eg][m]);
        ull t1 = dup2(S.st[eg + 16][m]);
#pragma unroll
        for (int u = 0; u < 4; u++) {
            ull w = *(const ull*)&S.sw2[m][(cg + 16 * u) * 2];
            acc[0][u] = ffma2(t0, w, acc[0][u]);
            acc[1][u] = ffma2(t1, w, acc[1][u]);
        }
    }
    float* out = table + (size_t)conv * TBL * NB + (size_t)e_base * NB;
#pragma unroll
    for (int u = 0; u < 4; u++) {
        int c = (cg + 16 * u) * 2;
        *(float2*)&out[(size_t)eg * NB + c]        = unpack2(acc[0][u]);
        *(float2*)&out[(size_t)(eg + 16) * NB + c] = unpack2(acc[1][u]);
    }
}

// ---------------- edge gather: agg[dst] = sum_e hf[src_e] * W(d_e) ----------------
__global__ void __launch_bounds__(256)
gather_kernel(const int* __restrict__ off, const int* __restrict__ srcs,
              const float* __restrict__ tf, const float* __restrict__ table,
              const float* __restrict__ hf, float* __restrict__ agg) {
    int w = (blockIdx.x * 256 + threadIdx.x) >> 5;
    int lane = threadIdx.x & 31;
    if (w >= N_ATOMS) return;
    int s = off[w], t = off[w + 1];
    float4 acc = make_float4(0.f, 0.f, 0.f, 0.f);
    for (int j = s; j < t; j++) {
        int src = __ldg(&srcs[j]);
        float tfv = __ldg(&tf[j]);
        int i0 = (int)tfv;
        float f = tfv - (float)i0;
        const float4* t0 = (const float4*)(table + (size_t)i0 * NB);
        float4 w0 = __ldg(&t0[lane]);
        float4 w1 = __ldg(&t0[lane + 32]);   // row i0+1 (contiguous)
        float4 hv = __ldg(&((const float4*)(hf + (size_t)src * NB))[lane]);
        float wx = w0.x + f * (w1.x - w0.x);
        float wy = w0.y + f * (w1.y - w0.y);
        float wz = w0.z + f * (w1.z - w0.z);
        float ww = w0.w + f * (w1.w - w0.w);
        acc.x += wx * hv.x;
        acc.y += wy * hv.y;
        acc.z += wz * hv.z;
        acc.w += ww * hv.w;
    }
    ((float4*)(agg + (size_t)w * NB))[lane] = acc;
}

// ---------------- generic fused GEMM: C = [ssp](A @ B + bias) [+= C] ----------------
template<int COLS>
struct GemmSmem {
    ull   sA2[128][64 + 2];       // dup-transposed A tile
    float sB[128][COLS];
    float sbias[COLS];
};

template<int COLS, bool ACT, bool RES>
__global__ void __launch_bounds__(256, 1)
gemm_kernel(const float* __restrict__ A, const float* __restrict__ B,
            const float* __restrict__ bias, float* __restrict__ C, int N) {
    extern __shared__ char smem_raw[];
    GemmSmem<COLS>& S = *reinterpret_cast<GemmSmem<COLS>*>(smem_raw);
    const int tid = threadIdx.x;
    const int row0 = blockIdx.x * 64;

    for (int idx = tid; idx < 128 * COLS / 4; idx += 256)
        ((float4*)S.sB)[idx] = ((const float4*)B)[idx];
    if (tid < COLS) S.sbias[tid] = bias[tid];

    for (int idx = tid; idx < 64 * 32; idx += 256) {
        int rr = idx >> 5;
        int k4 = idx & 31;
        float4 v = make_float4(0.f, 0.f, 0.f, 0.f);
        if (row0 + rr < N) v = ((const float4*)(A + (size_t)(row0 + rr) * 128))[k4];
        int k = k4 * 4;
        S.sA2[k + 0][rr] = dup2(v.x);
        S.sA2[k + 1][rr] = dup2(v.y);
        S.sA2[k + 2][rr] = dup2(v.z);
        S.sA2[k + 3][rr] = dup2(v.w);
    }
    __syncthreads();

    const int eg = tid >> 4;       // row group: 4 rows
    const int jg = tid & 15;       // col group: pairs at jg*2 + 32u
    const int r0 = eg * 4;
    constexpr int NU = COLS / 32;

    ull acc[4][NU];
#pragma unroll
    for (int u = 0; u < NU; u++) {
        ull b0 = *(const ull*)&S.sbias[jg * 2 + 32 * u];
#pragma unroll
        for (int r = 0; r < 4; r++) acc[r][u] = b0;
    }

#pragma unroll 4
    for (int k = 0; k < 128; k++) {
        ulonglong2 ta = *(const ulonglong2*)&S.sA2[k][r0];
        ulonglong2 tb = *(const ulonglong2*)&S.sA2[k][r0 + 2];
#pragma unroll
        for (int u = 0; u < NU; u++) {
            ull w = *(const ull*)&S.sB[k][jg * 2 + 32 * u];
            acc[0][u] = ffma2(ta.x, w, acc[0][u]);
            acc[1][u] = ffma2(ta.y, w, acc[1][u]);
            acc[2][u] = ffma2(tb.x, w, acc[2][u]);
            acc[3][u] = ffma2(tb.y, w, acc[3][u]);
        }
    }

#pragma unroll
    for (int r = 0; r < 4; r++) {
        int row = row0 + r0 + r;
        if (row >= N) continue;
#pragma unroll
        for (int u = 0; u < NU; u++) {
            int c = jg * 2 + 32 * u;
            float2 v = unpack2(acc[r][u]);
            if (ACT) { v.x = sspf(v.x); v.y = sspf(v.y); }
            float2* cp = (float2*)&C[(size_t)row * COLS + c];
            if (RES) { float2 o = *cp; v.x += o.x; v.y += o.y; }
            *cp = v;
        }
    }
}

// ---------------- readout: per-atom dot, then deterministic group sums ----------------
__global__ void final_dot_kernel(const float* __restrict__ z, const float* __restrict__ aw2,
                                 float* __restrict__ y) {
    int atom = (blockIdx.x * 256 + threadIdx.x) >> 5;
    int lane = threadIdx.x & 31;
    if (atom >= N_ATOMS) return;
    const float* zr = z + (size_t)atom * 64;
    float v = zr[lane] * aw2[lane] + zr[lane + 32] * aw2[lane + 32];
#pragma unroll
    for (int o = 16; o > 0; o >>= 1) v += __shfl_xor_sync(0xffffffffu, v, o);
    if (lane == 0) y[atom] = v;
}

__global__ void group_sum_kernel(const float* __restrict__ y, const float* __restrict__ ab2,
                                 float* __restrict__ out) {
    __shared__ float s[256];
    int g = blockIdx.x;
    int t = threadIdx.x;
    const float* yg = y + (size_t)g * NPER;
    float acc = 0.f;
    for (int i = t; i < NPER; i += 256) acc += yg[i];   // fixed order -> deterministic
    s[t] = acc;
    __syncthreads();
    for (int o = 128; o > 0; o >>= 1) {
        if (t < o) s[t] += s[t + o];
        __syncthreads();
    }
    if (t == 0) out[g] = s[0] + (float)NPER * ab2[0];
}

// ---------------- host launch ----------------
extern "C" void kernel_launch(void* const* d_in, const int* in_sizes, int n_in,
                              void* d_out, int out_size) {
    const int*   r    = (const int*)d_in[0];
    const float* xyz  = (const float*)d_in[1];
    const int*   a    = (const int*)d_in[2];
    int wi = (in_sizes[3] == 1) ? 4 : 3;   // skip n_per scalar if present
    const float* embed = (const float*)d_in[wi + 0];
    const float* fw1   = (const float*)d_in[wi + 1];
    const float* fb1   = (const float*)d_in[wi + 2];
    const float* fw2   = (const float*)d_in[wi + 3];
    const float* fb2   = (const float*)d_in[wi + 4];
    const float* afw   = (const float*)d_in[wi + 5];
    const float* afb   = (const float*)d_in[wi + 6];
    const float* ow1   = (const float*)d_in[wi + 7];
    const float* ob1   = (const float*)d_in[wi + 8];
    const float* ow2   = (const float*)d_in[wi + 9];
    const float* ob2   = (const float*)d_in[wi + 10];
    const float* aw1   = (const float*)d_in[wi + 11];
    const float* ab1   = (const float*)d_in[wi + 12];
    const float* aw2   = (const float*)d_in[wi + 13];
    const float* ab2   = (const float*)d_in[wi + 14];

    float *h_p, *hf_p, *agg_p, *u_p, *z_p, *y_p, *dist_p, *tab_p, *tf_p;
    int *deg_p, *cur_p, *off_p, *eidx_p, *srcs_p, *bsum_p, *boff_p;
    cudaGetSymbolAddress((void**)&h_p,    d_h);
    cudaGetSymbolAddress((void**)&hf_p,   d_hf);
    cudaGetSymbolAddress((void**)&agg_p,  d_agg);
    cudaGetSymbolAddress((void**)&u_p,    d_u);
    cudaGetSymbolAddress((void**)&z_p,    d_z);
    cudaGetSymbolAddress((void**)&y_p,    d_y);
    cudaGetSymbolAddress((void**)&dist_p, d_dist);
    cudaGetSymbolAddress((void**)&tab_p,  d_table);
    cudaGetSymbolAddress((void**)&deg_p,  d_deg);
    cudaGetSymbolAddress((void**)&cur_p,  d_cur);
    cudaGetSymbolAddress((void**)&off_p,  d_off);
    cudaGetSymbolAddress((void**)&eidx_p, d_eidx);
    cudaGetSymbolAddress((void**)&srcs_p, d_srcs);
    cudaGetSymbolAddress((void**)&tf_p,   d_tf);
    cudaGetSymbolAddress((void**)&bsum_p, d_bsum);
    cudaGetSymbolAddress((void**)&boff_p, d_boff);

    cudaFuncSetAttribute(gemm_kernel<128, false, false>, cudaFuncAttributeMaxDynamicSharedMemorySize, (int)sizeof(GemmSmem<128>));
    cudaFuncSetAttribute(gemm_kernel<128, true,  false>, cudaFuncAttributeMaxDynamicSharedMemorySize, (int)sizeof(GemmSmem<128>));
    cudaFuncSetAttribute(gemm_kernel<128, false, true >, cudaFuncAttributeMaxDynamicSharedMemorySize, (int)sizeof(GemmSmem<128>));
    cudaFuncSetAttribute(gemm_kernel<64,  true,  false>, cudaFuncAttributeMaxDynamicSharedMemorySize, (int)sizeof(GemmSmem<64>));
    cudaFuncSetAttribute(build_table_kernel, cudaFuncAttributeMaxDynamicSharedMemorySize, (int)sizeof(TblSmem));

    const int GEMM_GRID = (N_ATOMS + 63) / 64;
    const int EB = (N_EDGES + 255) / 256;   // 3125
    const int AB = (N_ATOMS + 255) / 256;   // 196
    const int WARP_GRID = (N_ATOMS * 32 + 255) / 256;  // warp per atom

    // launch order arranged so that launch index 5 (ncu -s 5 -c 1) = first NB GEMM
    cudaMemsetAsync(deg_p, 0, sizeof(int) * N_ATOMS, 0);                     // 0
    cudaMemsetAsync(cur_p, 0, sizeof(int) * N_ATOMS, 0);                     // 1
    init_h_kernel<<<(N_ATOMS * 32 + 255) / 256, 256>>>(r, embed, h_p);       // 2
    d_count_kernel<<<EB, 256>>>(xyz, a, dist_p, deg_p);                      // 3
    scan_bsum_kernel<<<AB, 256>>>(deg_p, bsum_p);                            // 4
    gemm_kernel<128, false, false><<<GEMM_GRID, 256, sizeof(GemmSmem<128>)>>>(  // 5 <- profiled
        h_p, afw, afb, hf_p, N_ATOMS);
    scan_boff_kernel<<<1, 256>>>(bsum_p, boff_p, AB);                        // 6
    scan_off_kernel<<<AB, 256>>>(deg_p, boff_p, off_p);                      // 7
    fill_kernel<<<EB, 256>>>(a, off_p, cur_p, eidx_p);                       // 8
    sort_finalize_kernel<<<AB, 256>>>(off_p, eidx_p, a, dist_p, srcs_p, tf_p); // 9
    {
        dim3 g(TBL / ENT, 3);
        build_table_kernel<<<g, 256, sizeof(TblSmem)>>>(fw1, fb1, fw2, fb2, tab_p); // 10
    }

    for (int i = 0; i < 3; i++) {
        if (i > 0) {
            gemm_kernel<128, false, false><<<GEMM_GRID, 256, sizeof(GemmSmem<128>)>>>(
                h_p, afw + (size_t)i * 128 * 128, afb + (size_t)i * 128, hf_p, N_ATOMS);
        }
        gather_kernel<<<WARP_GRID, 256>>>(off_p, srcs_p, tf_p,
                                          tab_p + (size_t)i * TBL * NB, hf_p, agg_p);
        gemm_kernel<128, true, false><<<GEMM_GRID, 256, sizeof(GemmSmem<128>)>>>(
            agg_p, ow1 + (size_t)i * 128 * 128, ob1 + (size_t)i * 128, u_p, N_ATOMS);
        gemm_kernel<128, false, true><<<GEMM_GRID, 256, sizeof(GemmSmem<128>)>>>(
            u_p, ow2 + (size_t)i * 128 * 128, ob2 + (size_t)i * 128, h_p, N_ATOMS);
    }

    gemm_kernel<64, true, false><<<GEMM_GRID, 256, sizeof(GemmSmem<64>)>>>(
        h_p, aw1, ab1, z_p, N_ATOMS);
    final_dot_kernel<<<WARP_GRID, 256>>>(z_p, aw2, y_p);
    group_sum_kernel<<<10, 256>>>(y_p, ab2, (float*)d_out);
}

// round 6
// speedup vs baseline: 1.2906x; 1.2020x over previous
#include <cuda_runtime.h>
#include <cuda_bf16.h>
#include <math.h>
#include <stdint.h>

// ---------------- problem constants ----------------
#define N_ATOMS 50000
#define N_EDGES 800000
#define NB 128
#define NG 32
#define NPER 5000
#define TBL 8192                 // table entries per conv
#define DMAX 6.5f
#define ENT 32                   // entries per table-build block

typedef unsigned long long ull;

// ---------------- device scratch (static, no runtime alloc) ----------------
__device__ float d_h  [(size_t)N_ATOMS * NB];
__device__ float d_hf [(size_t)N_ATOMS * NB];
__device__ float d_agg[(size_t)N_ATOMS * NB];
__device__ float d_u  [(size_t)N_ATOMS * NB];
__device__ float d_z  [(size_t)N_ATOMS * 64];
__device__ float d_y  [N_ATOMS];
__device__ float d_dist[N_EDGES];
__device__ float d_table[(size_t)3 * TBL * NB];   // 12.6 MB
__device__ int   d_deg[N_ATOMS];
__device__ int   d_cur[N_ATOMS];
__device__ int   d_off[N_ATOMS + 1];
__device__ int   d_eidx[N_EDGES];
__device__ int   d_srcs[N_EDGES];    // src per CSR slot
__device__ float d_tf  [N_EDGES];    // table coord per CSR slot
__device__ int   d_bsum[256];
__device__ int   d_boff[256];

// ---------------- helpers ----------------
__device__ __forceinline__ ull ffma2(ull a, ull b, ull c) {
    ull d;
    asm("fma.rn.f32x2 %0, %1, %2, %3;" : "=l"(d) : "l"(a), "l"(b), "l"(c));
    return d;
}
__device__ __forceinline__ ull dup2(float x) {
    ull d; asm("mov.b64 %0, {%1, %1};" : "=l"(d) : "f"(x)); return d;
}
__device__ __forceinline__ float2 unpack2(ull v) {
    float2 r; asm("mov.b64 {%0, %1}, %2;" : "=f"(r.x), "=f"(r.y) : "l"(v)); return r;
}
__device__ __forceinline__ float sspf(float x) {
    // softplus(x) - log(2), numerically stable
    float ax = fabsf(x);
    return fmaxf(x, 0.0f) + log1pf(__expf(-ax)) - 0.69314718055994531f;
}

// ---------------- init h = embed[r] ----------------
__global__ void init_h_kernel(const int* __restrict__ r, const float* __restrict__ embed,
                              float* __restrict__ h) {
    int idx = blockIdx.x * blockDim.x + threadIdx.x;   // over float4 elements
    if (idx < N_ATOMS * (NB / 4)) {
        int row = idx >> 5;
        int c4  = idx & 31;
        int t = r[row];
        ((float4*)h)[idx] = ((const float4*)embed)[(size_t)t * 32 + c4];
    }
}

// ---------------- fused: per-edge distance + degree count ----------------
__global__ void d_count_kernel(const float* __restrict__ xyz, const int* __restrict__ a,
                               float* __restrict__ dist, int* __restrict__ deg) {
    int e = blockIdx.x * 256 + threadIdx.x;
    if (e < N_EDGES) {
        int2 ij = ((const int2*)a)[e];
        float dx = xyz[3 * ij.x + 0] - xyz[3 * ij.y + 0];
        float dy = xyz[3 * ij.x + 1] - xyz[3 * ij.y + 1];
        float dz = xyz[3 * ij.x + 2] - xyz[3 * ij.y + 2];
        dist[e] = sqrtf(dx * dx + dy * dy + dz * dz + 1e-12f);
        atomicAdd(&deg[ij.x], 1);
    }
}

// ---------------- hierarchical scan ----------------
__global__ void scan_bsum_kernel(const int* __restrict__ deg, int* __restrict__ bsum) {
    __shared__ int s[256];
    int t = threadIdx.x;
    int i = blockIdx.x * 256 + t;
    s[t] = (i < N_ATOMS) ? deg[i] : 0;
    __syncthreads();
    for (int o = 128; o > 0; o >>= 1) {
        if (t < o) s[t] += s[t + o];
        __syncthreads();
    }
    if (t == 0) bsum[blockIdx.x] = s[0];
}

__global__ void scan_boff_kernel(const int* __restrict__ bsum, int* __restrict__ boff, int nb) {
    __shared__ int s[256];
    int t = threadIdx.x;
    int v = (t < nb) ? bsum[t] : 0;
    s[t] = v;
    __syncthreads();
    for (int o = 1; o < 256; o <<= 1) {
        int u = (t >= o) ? s[t - o] : 0;
        __syncthreads();
        s[t] += u;
        __syncthreads();
    }
    if (t < nb) boff[t] = s[t] - v;   // exclusive
}

__global__ void scan_off_kernel(const int* __restrict__ deg, const int* __restrict__ boff,
                                int* __restrict__ off) {
    __shared__ int s[256];
    int t = threadIdx.x;
    int i = blockIdx.x * 256 + t;
    int v = (i < N_ATOMS) ? deg[i] : 0;
    s[t] = v;
    __syncthreads();
    for (int o = 1; o < 256; o <<= 1) {
        int u = (t >= o) ? s[t - o] : 0;
        __syncthreads();
        s[t] += u;
        __syncthreads();
    }
    if (i < N_ATOMS) off[i] = boff[blockIdx.x] + s[t] - v;  // exclusive
    if (blockIdx.x == 0 && t == 0) off[N_ATOMS] = N_EDGES;
}

__global__ void fill_kernel(const int* __restrict__ a, const int* __restrict__ off,
                            int* __restrict__ cur, int* __restrict__ eidx) {
    int e = blockIdx.x * 256 + threadIdx.x;
    if (e < N_EDGES) {
        int dst = a[2 * e];
        int p = off[dst] + atomicAdd(&cur[dst], 1);
        eidx[p] = e;
    }
}

// per-dst insertion sort (deterministic order) + materialize srcs/tf
__global__ void sort_finalize_kernel(const int* __restrict__ off, int* __restrict__ eidx,
                                     const int* __restrict__ a, const float* __restrict__ dist,
                                     int* __restrict__ srcs, float* __restrict__ tf) {
    int v = blockIdx.x * 256 + threadIdx.x;
    if (v < N_ATOMS) {
        int s = off[v], t = off[v + 1];
        for (int i = s + 1; i < t; i++) {
            int key = eidx[i];
            int j = i - 1;
            while (j >= s && eidx[j] > key) { eidx[j + 1] = eidx[j]; j--; }
            eidx[j + 1] = key;
        }
        const float SCALE = (float)(TBL - 1) / DMAX;
        for (int j = s; j < t; j++) {
            int e = eidx[j];
            srcs[j] = a[2 * e + 1];
            tf[j] = fminf(dist[e] * SCALE, (float)(TBL - 1) - 1e-3f);
        }
    }
}

// ---------------- build W(d) tables: ENT entries per block, weights in smem ----------------
struct TblSmem {
    float sw1[NG][NB];       // 16 KB
    float sw2[NB][NB];       // 64 KB
    float sg[ENT][NG];       // 4 KB
    float st[ENT][NB];       // 16 KB
    float sb1[NB];
    float sb2[NB];
};

__global__ void __launch_bounds__(256, 1)
build_table_kernel(const float* __restrict__ fw1, const float* __restrict__ fb1,
                   const float* __restrict__ fw2, const float* __restrict__ fb2,
                   float* __restrict__ table) {
    extern __shared__ char smem_raw[];
    TblSmem& S = *reinterpret_cast<TblSmem*>(smem_raw);
    const int tid = threadIdx.x;
    const int conv = blockIdx.y;
    const int e_base = blockIdx.x * ENT;

    const float* w1 = fw1 + (size_t)conv * NG * NB;
    const float* w2 = fw2 + (size_t)conv * NB * NB;
    for (int idx = tid; idx < NG * NB / 4; idx += 256)
        ((float4*)S.sw1)[idx] = ((const float4*)w1)[idx];
    for (int idx = tid; idx < NB * NB / 4; idx += 256)
        ((float4*)S.sw2)[idx] = ((const float4*)w2)[idx];
    if (tid < NB) { S.sb1[tid] = fb1[conv * NB + tid]; S.sb2[tid] = fb2[conv * NB + tid]; }

    // gaussians for ENT entries
    const float step = 5.0f / 31.0f;
    const float coeff = -0.5f / (step * step);
    const float dstep = DMAX / (float)(TBL - 1);
    for (int idx = tid; idx < ENT * NG; idx += 256) {
        int e = idx >> 5, k = idx & 31;
        float dd = (float)(e_base + e) * dstep - step * (float)k;
        S.sg[e][k] = __expf(coeff * dd * dd);
    }
    __syncthreads();

    // phase 1: st[e][c] = ssp(g[e] @ w1 + b1)
    for (int idx = tid; idx < ENT * NB; idx += 256) {
        int e = idx >> 7, c = idx & 127;
        float acc = S.sb1[c];
#pragma unroll
        for (int k = 0; k < NG; k++) acc += S.sg[e][k] * S.sw1[k][c];
        S.st[e][c] = sspf(acc);
    }
    __syncthreads();

    // phase 2: W[e][c] = st[e] @ w2 + b2 ; thread: 2 entries x 4 col-pairs
    const int eg = tid >> 4;              // 0..15 -> entries eg, eg+16
    const int cg = tid & 15;              // col pairs cg+16u (u=0..3)
    ull acc[2][4];
#pragma unroll
    for (int u = 0; u < 4; u++) {
        ull b0 = *(const ull*)&S.sb2[(cg + 16 * u) * 2];
        acc[0][u] = b0; acc[1][u] = b0;
    }
#pragma unroll 4
    for (int m = 0; m < NB; m++) {
        ull t0 = dup2(S.st[eg][m]);
        ull t1 = dup2(S.st[eg + 16][m]);
#pragma unroll
        for (int u = 0; u < 4; u++) {
            ull w = *(const ull*)&S.sw2[m][(cg + 16 * u) * 2];
            acc[0][u] = ffma2(t0, w, acc[0][u]);
            acc[1][u] = ffma2(t1, w, acc[1][u]);
        }
    }
    float* out = table + (size_t)conv * TBL * NB + (size_t)e_base * NB;
#pragma unroll
    for (int u = 0; u < 4; u++) {
        int c = (cg + 16 * u) * 2;
        *(float2*)&out[(size_t)eg * NB + c]        = unpack2(acc[0][u]);
        *(float2*)&out[(size_t)(eg + 16) * NB + c] = unpack2(acc[1][u]);
    }
}

// ---------------- edge gather: agg[dst] = sum_e hf[src_e] * W(d_e) ----------------
__global__ void __launch_bounds__(256)
gather_kernel(const int* __restrict__ off, const int* __restrict__ srcs,
              const float* __restrict__ tf, const float* __restrict__ table,
              const float* __restrict__ hf, float* __restrict__ agg) {
    int w = (blockIdx.x * 256 + threadIdx.x) >> 5;
    int lane = threadIdx.x & 31;
    if (w >= N_ATOMS) return;
    int s = off[w], t = off[w + 1];
    float4 acc = make_float4(0.f, 0.f, 0.f, 0.f);
    for (int j = s; j < t; j++) {
        int src = __ldg(&srcs[j]);
        float tfv = __ldg(&tf[j]);
        int i0 = (int)tfv;
        float f = tfv - (float)i0;
        const float4* t0 = (const float4*)(table + (size_t)i0 * NB);
        float4 w0 = __ldg(&t0[lane]);
        float4 w1 = __ldg(&t0[lane + 32]);   // row i0+1 (contiguous)
        float4 hv = __ldg(&((const float4*)(hf + (size_t)src * NB))[lane]);
        float wx = w0.x + f * (w1.x - w0.x);
        float wy = w0.y + f * (w1.y - w0.y);
        float wz = w0.z + f * (w1.z - w0.z);
        float ww = w0.w + f * (w1.w - w0.w);
        acc.x += wx * hv.x;
        acc.y += wy * hv.y;
        acc.z += wz * hv.z;
        acc.w += ww * hv.w;
    }
    ((float4*)(agg + (size_t)w * NB))[lane] = acc;
}

// ---------------- generic fused GEMM: C = [ssp](A @ B + bias) [+= C] ----------------
// A tile stored transposed WITHOUT duplication (35 KB); pair-dup done in registers.
// smem ~100 KB -> 2 CTAs/SM -> 4 warps/SMSP for latency hiding.
template<int COLS>
struct GemmSmem {
    float sAT[128][68];           // transposed A tile, +4 pad (keeps 16B alignment)
    float sB[128][COLS];
    float sbias[COLS];
};

template<int COLS, bool ACT, bool RES>
__global__ void __launch_bounds__(256, 2)
gemm_kernel(const float* __restrict__ A, const float* __restrict__ B,
            const float* __restrict__ bias, float* __restrict__ C, int N) {
    extern __shared__ char smem_raw[];
    GemmSmem<COLS>& S = *reinterpret_cast<GemmSmem<COLS>*>(smem_raw);
    const int tid = threadIdx.x;
    const int row0 = blockIdx.x * 64;

    for (int idx = tid; idx < 128 * COLS / 4; idx += 256)
        ((float4*)S.sB)[idx] = ((const float4*)B)[idx];
    if (tid < COLS) S.sbias[tid] = bias[tid];

    // load A tile transposed (no duplication)
    for (int idx = tid; idx < 64 * 32; idx += 256) {
        int rr = idx >> 5;
        int k4 = idx & 31;
        float4 v = make_float4(0.f, 0.f, 0.f, 0.f);
        if (row0 + rr < N) v = ((const float4*)(A + (size_t)(row0 + rr) * 128))[k4];
        int k = k4 * 4;
        S.sAT[k + 0][rr] = v.x;
        S.sAT[k + 1][rr] = v.y;
        S.sAT[k + 2][rr] = v.z;
        S.sAT[k + 3][rr] = v.w;
    }
    __syncthreads();

    const int eg = tid >> 4;       // row group: 4 rows
    const int jg = tid & 15;       // col group: pairs at jg*2 + 32u
    const int r0 = eg * 4;
    constexpr int NU = COLS / 32;

    ull acc[4][NU];
#pragma unroll
    for (int u = 0; u < NU; u++) {
        ull b0 = *(const ull*)&S.sbias[jg * 2 + 32 * u];
#pragma unroll
        for (int r = 0; r < 4; r++) acc[r][u] = b0;
    }

#pragma unroll 4
    for (int k = 0; k < 128; k++) {
        // one broadcast LDS.128: 4 A rows for this thread
        float4 av = *(const float4*)&S.sAT[k][r0];
        ull a0 = dup2(av.x), a1 = dup2(av.y), a2 = dup2(av.z), a3 = dup2(av.w);
#pragma unroll
        for (int u = 0; u < NU; u++) {
            ull w = *(const ull*)&S.sB[k][jg * 2 + 32 * u];
            acc[0][u] = ffma2(a0, w, acc[0][u]);
            acc[1][u] = ffma2(a1, w, acc[1][u]);
            acc[2][u] = ffma2(a2, w, acc[2][u]);
            acc[3][u] = ffma2(a3, w, acc[3][u]);
        }
    }

#pragma unroll
    for (int r = 0; r < 4; r++) {
        int row = row0 + r0 + r;
        if (row >= N) continue;
#pragma unroll
        for (int u = 0; u < NU; u++) {
            int c = jg * 2 + 32 * u;
            float2 v = unpack2(acc[r][u]);
            if (ACT) { v.x = sspf(v.x); v.y = sspf(v.y); }
            float2* cp = (float2*)&C[(size_t)row * COLS + c];
            if (RES) { float2 o = *cp; v.x += o.x; v.y += o.y; }
            *cp = v;
        }
    }
}

// ---------------- readout: per-atom dot, then deterministic group sums ----------------
__global__ void final_dot_kernel(const float* __restrict__ z, const float* __restrict__ aw2,
                                 float* __restrict__ y) {
    int atom = (blockIdx.x * 256 + threadIdx.x) >> 5;
    int lane = threadIdx.x & 31;
    if (atom >= N_ATOMS) return;
    const float* zr = z + (size_t)atom * 64;
    float v = zr[lane] * aw2[lane] + zr[lane + 32] * aw2[lane + 32];
#pragma unroll
    for (int o = 16; o > 0; o >>= 1) v += __shfl_xor_sync(0xffffffffu, v, o);
    if (lane == 0) y[atom] = v;
}

__global__ void group_sum_kernel(const float* __restrict__ y, const float* __restrict__ ab2,
                                 float* __restrict__ out) {
    __shared__ float s[256];
    int g = blockIdx.x;
    int t = threadIdx.x;
    const float* yg = y + (size_t)g * NPER;
    float acc = 0.f;
    for (int i = t; i < NPER; i += 256) acc += yg[i];   // fixed order -> deterministic
    s[t] = acc;
    __syncthreads();
    for (int o = 128; o > 0; o >>= 1) {
        if (t < o) s[t] += s[t + o];
        __syncthreads();
    }
    if (t == 0) out[g] = s[0] + (float)NPER * ab2[0];
}

// ---------------- host launch ----------------
extern "C" void kernel_launch(void* const* d_in, const int* in_sizes, int n_in,
                              void* d_out, int out_size) {
    const int*   r    = (const int*)d_in[0];
    const float* xyz  = (const float*)d_in[1];
    const int*   a    = (const int*)d_in[2];
    int wi = (in_sizes[3] == 1) ? 4 : 3;   // skip n_per scalar if present
    const float* embed = (const float*)d_in[wi + 0];
    const float* fw1   = (const float*)d_in[wi + 1];
    const float* fb1   = (const float*)d_in[wi + 2];
    const float* fw2   = (const float*)d_in[wi + 3];
    const float* fb2   = (const float*)d_in[wi + 4];
    const float* afw   = (const float*)d_in[wi + 5];
    const float* afb   = (const float*)d_in[wi + 6];
    const float* ow1   = (const float*)d_in[wi + 7];
    const float* ob1   = (const float*)d_in[wi + 8];
    const float* ow2   = (const float*)d_in[wi + 9];
    const float* ob2   = (const float*)d_in[wi + 10];
    const float* aw1   = (const float*)d_in[wi + 11];
    const float* ab1   = (const float*)d_in[wi + 12];
    const float* aw2   = (const float*)d_in[wi + 13];
    const float* ab2   = (const float*)d_in[wi + 14];

    float *h_p, *hf_p, *agg_p, *u_p, *z_p, *y_p, *dist_p, *tab_p, *tf_p;
    int *deg_p, *cur_p, *off_p, *eidx_p, *srcs_p, *bsum_p, *boff_p;
    cudaGetSymbolAddress((void**)&h_p,    d_h);
    cudaGetSymbolAddress((void**)&hf_p,   d_hf);
    cudaGetSymbolAddress((void**)&agg_p,  d_agg);
    cudaGetSymbolAddress((void**)&u_p,    d_u);
    cudaGetSymbolAddress((void**)&z_p,    d_z);
    cudaGetSymbolAddress((void**)&y_p,    d_y);
    cudaGetSymbolAddress((void**)&dist_p, d_dist);
    cudaGetSymbolAddress((void**)&tab_p,  d_table);
    cudaGetSymbolAddress((void**)&deg_p,  d_deg);
    cudaGetSymbolAddress((void**)&cur_p,  d_cur);
    cudaGetSymbolAddress((void**)&off_p,  d_off);
    cudaGetSymbolAddress((void**)&eidx_p, d_eidx);
    cudaGetSymbolAddress((void**)&srcs_p, d_srcs);
    cudaGetSymbolAddress((void**)&tf_p,   d_tf);
    cudaGetSymbolAddress((void**)&bsum_p, d_bsum);
    cudaGetSymbolAddress((void**)&boff_p, d_boff);

    cudaFuncSetAttribute(gemm_kernel<128, false, false>, cudaFuncAttributeMaxDynamicSharedMemorySize, (int)sizeof(GemmSmem<128>));
    cudaFuncSetAttribute(gemm_kernel<128, true,  false>, cudaFuncAttributeMaxDynamicSharedMemorySize, (int)sizeof(GemmSmem<128>));
    cudaFuncSetAttribute(gemm_kernel<128, false, true >, cudaFuncAttributeMaxDynamicSharedMemorySize, (int)sizeof(GemmSmem<128>));
    cudaFuncSetAttribute(gemm_kernel<64,  true,  false>, cudaFuncAttributeMaxDynamicSharedMemorySize, (int)sizeof(GemmSmem<64>));
    cudaFuncSetAttribute(build_table_kernel, cudaFuncAttributeMaxDynamicSharedMemorySize, (int)sizeof(TblSmem));

    const int GEMM_GRID = (N_ATOMS + 63) / 64;
    const int EB = (N_EDGES + 255) / 256;   // 3125
    const int AB = (N_ATOMS + 255) / 256;   // 196
    const int WARP_GRID = (N_ATOMS * 32 + 255) / 256;  // warp per atom

    // launch order arranged so that launch index 5 (ncu -s 5 -c 1) = first NB GEMM
    cudaMemsetAsync(deg_p, 0, sizeof(int) * N_ATOMS, 0);                     // 0
    cudaMemsetAsync(cur_p, 0, sizeof(int) * N_ATOMS, 0);                     // 1
    init_h_kernel<<<(N_ATOMS * 32 + 255) / 256, 256>>>(r, embed, h_p);       // 2
    d_count_kernel<<<EB, 256>>>(xyz, a, dist_p, deg_p);                      // 3
    scan_bsum_kernel<<<AB, 256>>>(deg_p, bsum_p);                            // 4
    gemm_kernel<128, false, false><<<GEMM_GRID, 256, sizeof(GemmSmem<128>)>>>(  // 5 <- profiled
        h_p, afw, afb, hf_p, N_ATOMS);
    scan_boff_kernel<<<1, 256>>>(bsum_p, boff_p, AB);                        // 6
    scan_off_kernel<<<AB, 256>>>(deg_p, boff_p, off_p);                      // 7
    fill_kernel<<<EB, 256>>>(a, off_p, cur_p, eidx_p);                       // 8
    sort_finalize_kernel<<<AB, 256>>>(off_p, eidx_p, a, dist_p, srcs_p, tf_p); // 9
    {
        dim3 g(TBL / ENT, 3);
        build_table_kernel<<<g, 256, sizeof(TblSmem)>>>(fw1, fb1, fw2, fb2, tab_p); // 10
    }

    for (int i = 0; i < 3; i++) {
        if (i > 0) {
            gemm_kernel<128, false, false><<<GEMM_GRID, 256, sizeof(GemmSmem<128>)>>>(
                h_p, afw + (size_t)i * 128 * 128, afb + (size_t)i * 128, hf_p, N_ATOMS);
        }
        gather_kernel<<<WARP_GRID, 256>>>(off_p, srcs_p, tf_p,
                                          tab_p + (size_t)i * TBL * NB, hf_p, agg_p);
        gemm_kernel<128, true, false><<<GEMM_GRID, 256, sizeof(GemmSmem<128>)>>>(
            agg_p, ow1 + (size_t)i * 128 * 128, ob1 + (size_t)i * 128, u_p, N_ATOMS);
        gemm_kernel<128, false, true><<<GEMM_GRID, 256, sizeof(GemmSmem<128>)>>>(
            u_p, ow2 + (size_t)i * 128 * 128, ob2 + (size_t)i * 128, h_p, N_ATOMS);
    }

    gemm_kernel<64, true, false><<<GEMM_GRID, 256, sizeof(GemmSmem<64>)>>>(
        h_p, aw1, ab1, z_p, N_ATOMS);
    final_dot_kernel<<<WARP_GRID, 256>>>(z_p, aw2, y_p);
    group_sum_kernel<<<10, 256>>>(y_p, ab2, (float*)d_out);
}